// round 6
// baseline (speedup 1.0000x reference)
#include <cuda_runtime.h>

#define NB   2048
#define SRC  64
#define PAD  32

#define FMAGIC 8388608.0f   // 2^23
// fold: idx = by*64 + bx + KFOLD  where bx/by are float bits of (coord + 2^23),
// equals (y0-32)*64 + (x0-32) - 2048 ... precisely (y0*64+x0) - (32*64+32) with
// the 0x4B000000 bias removed:  KFOLD = -(0x4B000000*65 + 2080) mod 2^32
#define KFOLD (0u - (0x4B000000u * 65u + 2080u))

// smem: 4096 float4 entries, entry (y*64+x) = {f[y][x], s[y][x], f[y][x+1], s[y][x+1]}
extern __shared__ float4 s4[];

__global__ void __launch_bounds__(512, 3)
affine_sampler_kernel(const float* __restrict__ affine,   // (N,6)
                      const float* __restrict__ fill,     // (N,64,64)
                      const float* __restrict__ stroke,   // (N,64,64)
                      float* __restrict__ out_fill,       // (N,128,128)
                      float* __restrict__ out_stroke)     // (N,128,128)
{
    const int n   = blockIdx.x;
    const int tid = threadIdx.x;

    // ---- stage: build tap-pair float4 tiles (coalesced float4 reads + shfl) ----
    {
        const float4* gf = (const float4*)(fill   + (size_t)n * SRC * SRC);
        const float4* gs = (const float4*)(stroke + (size_t)n * SRC * SRC);
        #pragma unroll
        for (int i = 0; i < 2; i++) {
            const int v = tid + i * 512;        // float4 chunk 0..1023; x0=(v&15)*4, y=v>>4
            float4 f  = gf[v];
            float4 st = gs[v];
            // next chunk's first elems (same row except at row-end lanes, where
            // the produced entry is x=63 whose .zw is never consumed)
            float fnx = __shfl_down_sync(0xffffffffu, f.x,  1);
            float snx = __shfl_down_sync(0xffffffffu, st.x, 1);
            const int e = v * 4;
            s4[e + 0] = make_float4(f.x, st.x, f.y, st.y);
            s4[e + 1] = make_float4(f.y, st.y, f.z, st.z);
            s4[e + 2] = make_float4(f.z, st.z, f.w, st.w);
            s4[e + 3] = make_float4(f.w, st.w, fnx, snx);
        }
    }

    // ---- theta (broadcast loads; every thread computes) ----
    const float* a = affine + n * 6;
    const float a00 = 2.0f / (1.0f + __expf(-a[0]));
    const float a11 = 2.0f / (1.0f + __expf(-a[1]));
    const float a01 = 2.0f * tanhf(a[2]);
    const float a10 = 2.0f * tanhf(a[3]);
    const float a02 = tanhf(a[4]);
    const float a12 = tanhf(a[5]);

    // Folded chain: ix = a00*x + a01*y + Cx  (pixel coords in padded 128x128 img)
    const float Cx = 64.0f * a02 + 63.5f - 63.5f * (a00 + a01);
    const float Cy = 64.0f * a12 + 63.5f - 63.5f * (a10 + a11);

    // row-endpoint deltas (x = 0..127); a00 > 0 always, a10 sign unknown
    const float ex = 127.0f * a00;
    const float ey = 127.0f * a10;

    __syncthreads();

    float* of = out_fill   + (size_t)n * 128 * 128;
    float* os = out_stroke + (size_t)n * 128 * 128;

    const int lane = tid & 31;
    const int warp = tid >> 5;              // 0..15; warp owns whole rows
    const float xf = (float)(lane << 2);    // 4 contiguous pixels per lane

    #pragma unroll 1
    for (int it = 0; it < 8; it++) {
        const int   row = it * 16 + warp;
        const float yf  = (float)row;

        // row-start coords (x=0) and row extremes over x in [0,127]
        const float rx0 = fmaf(a01, yf, Cx);
        const float ry0 = fmaf(a11, yf, Cy);
        const float lox = rx0;               // a00 > 0
        const float hix = rx0 + ex;
        const float loy = fminf(ry0, ry0 + ey);
        const float hiy = fmaxf(ry0, ry0 + ey);

        // warp-uniform classification with fp-safety margins
        const bool inside = (lox >= 32.01f) & (hix <= 94.99f) &
                            (loy >= 32.01f) & (hiy <= 94.99f);
        const bool zero   = (hix <= 30.99f) | (lox >= 96.01f) |
                            (hiy <= 30.99f) | (loy >= 96.01f);

        const int o = row * 128 + (lane << 2);

        float ix = fmaf(a00, xf, rx0);
        float iy = fmaf(a10, xf, ry0);

        float4 rf, rs;
        float* rfp = &rf.x;
        float* rsp = &rs.x;

        if (inside) {
            // ---- fast interior path ----
            #pragma unroll
            for (int k = 0; k < 4; k++) {
                // magic-number floor (coords guaranteed in [32,95))
                const float tx = __fadd_rz(ix, FMAGIC);
                const float ty = __fadd_rz(iy, FMAGIC);
                const float fx0 = tx - FMAGIC;
                const float fy0 = ty - FMAGIC;
                const float wx = ix - fx0;
                const float wy = iy - fy0;
                const float mx = 1.0f - wx;
                const float my = 1.0f - wy;

                const unsigned bx = (unsigned)__float_as_int(tx);
                const unsigned by = (unsigned)__float_as_int(ty);
                const unsigned idx = by * 64u + bx + KFOLD;   // (y0-32)*64 + (x0-32)

                const float4 r0 = s4[idx];        // f00 s00 f10 s10
                const float4 r1 = s4[idx + 64];   // f01 s01 f11 s11

                const float w00 = mx * my, w10 = wx * my;
                const float w01 = mx * wy, w11 = wx * wy;

                float fv = r0.x * w00, sv = r0.y * w00;
                fv = fmaf(r0.z, w10, fv); sv = fmaf(r0.w, w10, sv);
                fv = fmaf(r1.x, w01, fv); sv = fmaf(r1.y, w01, sv);
                fv = fmaf(r1.z, w11, fv); sv = fmaf(r1.w, w11, sv);

                rfp[k] = fv;
                rsp[k] = sv;
                ix += a00;
                iy += a10;
            }
            __stcs((float4*)&of[o], rf);
            __stcs((float4*)&os[o], rs);
        } else if (zero) {
            // ---- all-zero row ----
            const float4 z = make_float4(0.f, 0.f, 0.f, 0.f);
            __stcs((float4*)&of[o], z);
            __stcs((float4*)&os[o], z);
        } else {
            // ---- generic boundary path (predicated taps; rare) ----
            #pragma unroll
            for (int k = 0; k < 4; k++) {
                const int x0 = __float2int_rd(ix);
                const int y0 = __float2int_rd(iy);
                const float wx = ix - (float)x0;
                const float wy = iy - (float)y0;
                const float mx = 1.0f - wx;
                const float my = 1.0f - wy;

                const bool vx0 = (unsigned)(x0 - PAD)     < 64u;
                const bool vx1 = (unsigned)(x0 - PAD + 1) < 64u;
                const bool vy0 = (unsigned)(y0 - PAD)     < 64u;
                const bool vy1 = (unsigned)(y0 - PAD + 1) < 64u;

                const int i00 = (y0 - PAD) * SRC + (x0 - PAD);

                float fv = 0.0f, sv = 0.0f;
                if (vx0 & vy0) { float4 r = s4[i00];      float w = mx * my; fv = fmaf(r.x, w, fv); sv = fmaf(r.y, w, sv); }
                if (vx1 & vy0) { float4 r = s4[i00 + 1];  float w = wx * my; fv = fmaf(r.x, w, fv); sv = fmaf(r.y, w, sv); }
                if (vx0 & vy1) { float4 r = s4[i00 + 64]; float w = mx * wy; fv = fmaf(r.x, w, fv); sv = fmaf(r.y, w, sv); }
                if (vx1 & vy1) { float4 r = s4[i00 + 65]; float w = wx * wy; fv = fmaf(r.x, w, fv); sv = fmaf(r.y, w, sv); }

                rfp[k] = fv;
                rsp[k] = sv;
                ix += a00;
                iy += a10;
            }
            __stcs((float4*)&of[o], rf);
            __stcs((float4*)&os[o], rs);
        }
    }
}

extern "C" void kernel_launch(void* const* d_in, const int* in_sizes, int n_in,
                              void* d_out, int out_size) {
    const float* affine = (const float*)d_in[0];   // (N,6) fp32
    const float* fill   = (const float*)d_in[1];   // (N,64,64) fp32
    const float* stroke = (const float*)d_in[2];   // (N,64,64) fp32
    // d_in[3] = targetsize (constant, unused)

    float* out_fill   = (float*)d_out;
    float* out_stroke = (float*)d_out + (size_t)NB * 128 * 128;

    const int smem_bytes = 4096 * sizeof(float4);  // 64 KB dynamic
    cudaFuncSetAttribute(affine_sampler_kernel,
                         cudaFuncAttributeMaxDynamicSharedMemorySize, smem_bytes);

    affine_sampler_kernel<<<NB, 512, smem_bytes>>>(affine, fill, stroke,
                                                   out_fill, out_stroke);
}